// round 11
// baseline (speedup 1.0000x reference)
#include <cuda_runtime.h>
#include <cuda_bf16.h>

// Problem constants
#define PB 2          // batch
#define PC 256        // channels
#define PN 4096       // D*H*W
#define PR 8          // low rank
#define PG 4          // groups
#define CG 64         // C/G

// Scratch (device globals; no allocations allowed)
__device__ float g_q[4][PR * PN];        // [prob][r][n]
__device__ float g_k[4][PN * PR];        // [prob][n][r]   (r contiguous, for vectorized dot)
__device__ float g_mx[4][PN];            // row max of logits
__device__ float g_invl[4][PN];          // 1 / sum exp
__device__ float g_vhat[4][PN * PC];     // [prob][n][c]   v scaled by invl, transposed

// ---------------------------------------------------------------------------
// K1: q,k projections. q[r,n] = sum_c w[r,c] x[c,n] + b[r]
// grid (PN/256, 8 slots), block 256. slot = (d<<2)|(b<<1)|proj
// ---------------------------------------------------------------------------
__global__ __launch_bounds__(256) void k1_qk(
    const float* __restrict__ fL, const float* __restrict__ fU,
    const float* __restrict__ qLw, const float* __restrict__ qLb,
    const float* __restrict__ kUw, const float* __restrict__ kUb,
    const float* __restrict__ qUw, const float* __restrict__ qUb,
    const float* __restrict__ kLw, const float* __restrict__ kLb)
{
    __shared__ float wst[PC * PR];   // transposed: wst[c*8+r]
    __shared__ float bs[PR];

    int slot = blockIdx.y;
    int d = slot >> 2, b = (slot >> 1) & 1, proj = slot & 1;
    const float *w, *bias, *x;
    if (d == 0) {
        if (proj == 0) { w = qLw; bias = qLb; x = fL; }
        else           { w = kUw; bias = kUb; x = fU; }
    } else {
        if (proj == 0) { w = qUw; bias = qUb; x = fU; }
        else           { w = kLw; bias = kLb; x = fL; }
    }
    int t = threadIdx.x;
    #pragma unroll
    for (int r = 0; r < PR; r++) wst[t * PR + r] = w[r * PC + t];
    if (t < PR) bs[t] = bias[t];
    __syncthreads();

    int n = blockIdx.x * 256 + t;
    const float* xb = x + b * (PC * PN);
    float acc[PR];
    #pragma unroll
    for (int r = 0; r < PR; r++) acc[r] = bs[r];

    #pragma unroll 4
    for (int c = 0; c < PC; c++) {
        float xv = xb[c * PN + n];
        float4 w0 = *(const float4*)&wst[c * PR];
        float4 w1 = *(const float4*)&wst[c * PR + 4];
        acc[0] = fmaf(w0.x, xv, acc[0]);
        acc[1] = fmaf(w0.y, xv, acc[1]);
        acc[2] = fmaf(w0.z, xv, acc[2]);
        acc[3] = fmaf(w0.w, xv, acc[3]);
        acc[4] = fmaf(w1.x, xv, acc[4]);
        acc[5] = fmaf(w1.y, xv, acc[5]);
        acc[6] = fmaf(w1.z, xv, acc[6]);
        acc[7] = fmaf(w1.w, xv, acc[7]);
    }

    int p = d * 2 + b;
    if (proj == 0) {
        #pragma unroll
        for (int r = 0; r < PR; r++) g_q[p][r * PN + n] = acc[r];
    } else {
        float4 o0 = make_float4(acc[0], acc[1], acc[2], acc[3]);
        float4 o1 = make_float4(acc[4], acc[5], acc[6], acc[7]);
        *(float4*)&g_k[p][n * PR]     = o0;
        *(float4*)&g_k[p][n * PR + 4] = o1;
    }
}

// ---------------------------------------------------------------------------
// K2: per-row softmax stats. One warp per row n: mx[n]=max_m s, invl[n]=1/sum exp(s-mx)
// grid (PN/8, 4 probs), block 256 (8 warps)
// ---------------------------------------------------------------------------
__device__ __forceinline__ float dot8(const float* qr, const float* kp) {
    float4 k0 = *(const float4*)kp;
    float4 k1 = *(const float4*)(kp + 4);
    float s = qr[0] * k0.x;
    s = fmaf(qr[1], k0.y, s);
    s = fmaf(qr[2], k0.z, s);
    s = fmaf(qr[3], k0.w, s);
    s = fmaf(qr[4], k1.x, s);
    s = fmaf(qr[5], k1.y, s);
    s = fmaf(qr[6], k1.z, s);
    s = fmaf(qr[7], k1.w, s);
    return s;
}

__global__ __launch_bounds__(256) void k2_stats()
{
    int p = blockIdx.y;
    int warp = threadIdx.x >> 5, lane = threadIdx.x & 31;
    int n = blockIdx.x * 8 + warp;
    const float* qg = g_q[p];
    const float* kg = g_k[p];

    float qr[PR];
    #pragma unroll
    for (int r = 0; r < PR; r++) qr[r] = qg[r * PN + n];

    float mloc = -1e30f;
    for (int m = lane; m < PN; m += 32) {
        float s = dot8(qr, &kg[m * PR]);
        mloc = fmaxf(mloc, s);
    }
    #pragma unroll
    for (int o = 16; o; o >>= 1)
        mloc = fmaxf(mloc, __shfl_xor_sync(0xFFFFFFFFu, mloc, o));

    float l = 0.0f;
    for (int m = lane; m < PN; m += 32) {
        float s = dot8(qr, &kg[m * PR]);
        l += __expf(s - mloc);
    }
    #pragma unroll
    for (int o = 16; o; o >>= 1)
        l += __shfl_xor_sync(0xFFFFFFFFu, l, o);

    if (lane == 0) {
        g_mx[p][n] = mloc;
        g_invl[p][n] = 1.0f / l;
    }
}

// ---------------------------------------------------------------------------
// K3: grouped 1x1 conv + invl scaling, output transposed:
//   vhat[n][c] = (sum_i w[g][co][i] * x[(g*64+i)][n] + vb[c]) * invl[n]
// grid (PN/64, 4 groups, 4 probs), block 256 (4x4 microtile per thread)
// ---------------------------------------------------------------------------
__global__ __launch_bounds__(256) void k3_v(
    const float* __restrict__ fL, const float* __restrict__ fU,
    const float* __restrict__ vUw, const float* __restrict__ vUb,
    const float* __restrict__ vLw, const float* __restrict__ vLb)
{
    __shared__ float wsT[CG * 65];   // wsT[i*65 + co]

    int p = blockIdx.z;
    int d = p >> 1, b = p & 1;
    int g = blockIdx.y;
    int n0 = blockIdx.x * 64;

    const float* w  = (d == 0) ? vUw : vLw;
    const float* vb = (d == 0) ? vUb : vLb;
    const float* x  = ((d == 0) ? fU : fL) + b * (PC * PN);

    int t = threadIdx.x;
    #pragma unroll
    for (int u = 0; u < 16; u++) {
        int lin = t + u * 256;                 // 0..4095
        int co = lin >> 6, i = lin & 63;
        wsT[i * 65 + co] = w[g * (CG * CG) + co * CG + i];
    }
    __syncthreads();

    int tx = t & 15, ty = t >> 4;
    float acc[4][4];
    #pragma unroll
    for (int j = 0; j < 4; j++)
        #pragma unroll
        for (int ii = 0; ii < 4; ii++) acc[j][ii] = 0.0f;

    const float* xg = x + g * CG * PN + n0 + ty * 4;
    #pragma unroll 8
    for (int i = 0; i < CG; i++) {
        float4 xv = *(const float4*)&xg[i * PN];
        int wb = i * 65 + tx * 4;
        float w0 = wsT[wb], w1 = wsT[wb + 1], w2 = wsT[wb + 2], w3 = wsT[wb + 3];
        acc[0][0] = fmaf(xv.x, w0, acc[0][0]);
        acc[0][1] = fmaf(xv.x, w1, acc[0][1]);
        acc[0][2] = fmaf(xv.x, w2, acc[0][2]);
        acc[0][3] = fmaf(xv.x, w3, acc[0][3]);
        acc[1][0] = fmaf(xv.y, w0, acc[1][0]);
        acc[1][1] = fmaf(xv.y, w1, acc[1][1]);
        acc[1][2] = fmaf(xv.y, w2, acc[1][2]);
        acc[1][3] = fmaf(xv.y, w3, acc[1][3]);
        acc[2][0] = fmaf(xv.z, w0, acc[2][0]);
        acc[2][1] = fmaf(xv.z, w1, acc[2][1]);
        acc[2][2] = fmaf(xv.z, w2, acc[2][2]);
        acc[2][3] = fmaf(xv.z, w3, acc[2][3]);
        acc[3][0] = fmaf(xv.w, w0, acc[3][0]);
        acc[3][1] = fmaf(xv.w, w1, acc[3][1]);
        acc[3][2] = fmaf(xv.w, w2, acc[3][2]);
        acc[3][3] = fmaf(xv.w, w3, acc[3][3]);
    }

    float bias[4];
    #pragma unroll
    for (int ii = 0; ii < 4; ii++) bias[ii] = vb[g * CG + tx * 4 + ii];

    float* vout = g_vhat[p];
    #pragma unroll
    for (int j = 0; j < 4; j++) {
        int n = n0 + ty * 4 + j;
        float il = g_invl[p][n];
        float4 o;
        o.x = (acc[j][0] + bias[0]) * il;
        o.y = (acc[j][1] + bias[1]) * il;
        o.z = (acc[j][2] + bias[2]) * il;
        o.w = (acc[j][3] + bias[3]) * il;
        *(float4*)&vout[n * PC + g * CG + tx * 4] = o;
    }
}

// ---------------------------------------------------------------------------
// K4: fused attend GEMM.  out[c,m] = f[c,m] + beta * sum_n vhat[n,c]*exp(s[n,m]-mx[n])
// 128x128 block tile, TN=32 n-chunk, 256 threads, 8x8 microtile.
// grid (PN/128 m-tiles, PC/128 c-tiles, 4 probs)
// ---------------------------------------------------------------------------
#define TN 32

__global__ __launch_bounds__(256, 2) void k4_attend(
    const float* __restrict__ fL, const float* __restrict__ fU,
    const float* __restrict__ beta_p, float* __restrict__ out)
{
    __shared__ float As[TN][128];    // vhat tile: As[ni][ci]
    __shared__ float Bs[TN][128];    // p tile:   Bs[ni][mi]
    __shared__ float qs[PR][TN];
    __shared__ float ks[PR][128];
    __shared__ float mxs[TN];

    const int t = threadIdx.x;
    const int p = blockIdx.z;
    const int d = p >> 1, b = p & 1;
    const int m0 = blockIdx.x * 128;
    const int c0 = blockIdx.y * 128;

    const float* qg  = g_q[p];
    const float* kg  = g_k[p];
    const float* vg  = g_vhat[p];
    const float* mxg = g_mx[p];

    // load K slice for this m-tile once
    #pragma unroll
    for (int u = 0; u < 4; u++) {
        int lin = t + u * 256;            // 0..1023
        int mi = lin >> 3, r = lin & 7;
        ks[r][mi] = kg[(m0 + mi) * PR + r];
    }
    __syncthreads();

    const int mi_fix = t & 127;
    float kreg[PR];
    #pragma unroll
    for (int r = 0; r < PR; r++) kreg[r] = ks[r][mi_fix];

    const int tx = t & 15, ty = t >> 4;
    float acc[8][8];
    #pragma unroll
    for (int i = 0; i < 8; i++)
        #pragma unroll
        for (int j = 0; j < 8; j++) acc[i][j] = 0.0f;

    for (int n0 = 0; n0 < PN; n0 += TN) {
        __syncthreads();   // protect smem from previous iteration's readers
        // load As (vhat tile) 32x128
        #pragma unroll
        for (int u = 0; u < 4; u++) {
            int lin = t + u * 256;         // 0..1023 float4s
            int row = lin >> 5, colv = lin & 31;
            *(float4*)&As[row][colv * 4] =
                *(const float4*)&vg[(n0 + row) * PC + c0 + colv * 4];
        }
        // load q slice 8x32 and mx
        {
            int r = t >> 5, ni = t & 31;
            qs[r][ni] = qg[r * PN + n0 + ni];
        }
        if (t < TN) mxs[t] = mxg[n0 + t];
        __syncthreads();

        // compute p tile: Bs[ni][mi] = exp(q.k - mx)
        #pragma unroll
        for (int v = 0; v < 16; v++) {
            int ni = ((t >> 7) + 2 * v) & 31;
            float s = -mxs[ni];
            #pragma unroll
            for (int r = 0; r < PR; r++) s = fmaf(qs[r][ni], kreg[r], s);
            Bs[ni][mi_fix] = __expf(s);
        }
        __syncthreads();

        // GEMM accumulate
        #pragma unroll 8
        for (int kk = 0; kk < TN; kk++) {
            float a[8], bb[8];
            *(float4*)&a[0]  = *(float4*)&As[kk][ty * 4];
            *(float4*)&a[4]  = *(float4*)&As[kk][64 + ty * 4];
            *(float4*)&bb[0] = *(float4*)&Bs[kk][tx * 4];
            *(float4*)&bb[4] = *(float4*)&Bs[kk][64 + tx * 4];
            #pragma unroll
            for (int i = 0; i < 8; i++)
                #pragma unroll
                for (int j = 0; j < 8; j++)
                    acc[i][j] = fmaf(a[i], bb[j], acc[i][j]);
        }
    }

    // epilogue: out = f + beta * acc
    const float beta = __ldg(beta_p);
    const float* fb = ((d == 0) ? fL : fU) + b * (PC * PN);
    float* ob = out + d * (PB * PC * PN) + b * (PC * PN);

    #pragma unroll
    for (int ih = 0; ih < 2; ih++) {
        #pragma unroll
        for (int i = 0; i < 4; i++) {
            int c = c0 + ih * 64 + ty * 4 + i;
            #pragma unroll
            for (int jh = 0; jh < 2; jh++) {
                int m = m0 + jh * 64 + tx * 4;
                float4 f4 = *(const float4*)&fb[c * PN + m];
                float4 o;
                o.x = fmaf(beta, acc[ih * 4 + i][jh * 4 + 0], f4.x);
                o.y = fmaf(beta, acc[ih * 4 + i][jh * 4 + 1], f4.y);
                o.z = fmaf(beta, acc[ih * 4 + i][jh * 4 + 2], f4.z);
                o.w = fmaf(beta, acc[ih * 4 + i][jh * 4 + 3], f4.w);
                *(float4*)&ob[c * PN + m] = o;
            }
        }
    }
}

// ---------------------------------------------------------------------------
extern "C" void kernel_launch(void* const* d_in, const int* in_sizes, int n_in,
                              void* d_out, int out_size)
{
    const float* fL  = (const float*)d_in[0];
    const float* fU  = (const float*)d_in[1];
    const float* qLw = (const float*)d_in[2];
    const float* qLb = (const float*)d_in[3];
    const float* kUw = (const float*)d_in[4];
    const float* kUb = (const float*)d_in[5];
    const float* vUw = (const float*)d_in[6];
    const float* vUb = (const float*)d_in[7];
    const float* qUw = (const float*)d_in[8];
    const float* qUb = (const float*)d_in[9];
    const float* kLw = (const float*)d_in[10];
    const float* kLb = (const float*)d_in[11];
    const float* vLw = (const float*)d_in[12];
    const float* vLb = (const float*)d_in[13];
    const float* beta = (const float*)d_in[14];
    float* out = (float*)d_out;

    k1_qk<<<dim3(PN / 256, 8), 256>>>(fL, fU, qLw, qLb, kUw, kUb, qUw, qUb, kLw, kLb);
    k2_stats<<<dim3(PN / 8, 4), 256>>>();
    k3_v<<<dim3(PN / 64, PG, 4), 256>>>(fL, fU, vUw, vUb, vLw, vLb);
    k4_attend<<<dim3(PN / 128, PC / 128, 4), 256>>>(fL, fU, beta, out);
}

// round 12
// speedup vs baseline: 1.0018x; 1.0018x over previous
#include <cuda_runtime.h>
#include <cuda_bf16.h>

// Problem constants
#define PB 2          // batch
#define PC 256        // channels
#define PN 4096       // D*H*W
#define PR 8          // low rank
#define PG 4          // groups
#define CG 64         // C/G

// Scratch (device globals; no allocations allowed)
__device__ float g_q[4][PR * PN];        // [prob][r][n]
__device__ float g_k[4][PN * PR];        // [prob][n][r]   (r contiguous, for vectorized dot)
__device__ float g_mx[4][PN];            // row max of logits
__device__ float g_invl[4][PN];          // 1 / sum exp
__device__ float g_vhat[4][PN * PC];     // [prob][n][c]   v scaled by invl, transposed

// ---------------------------------------------------------------------------
// K1: q,k projections. q[r,n] = sum_c w[r,c] x[c,n] + b[r]
// grid (PN/256, 8 slots), block 256. slot = (d<<2)|(b<<1)|proj
// ---------------------------------------------------------------------------
__global__ __launch_bounds__(256) void k1_qk(
    const float* __restrict__ fL, const float* __restrict__ fU,
    const float* __restrict__ qLw, const float* __restrict__ qLb,
    const float* __restrict__ kUw, const float* __restrict__ kUb,
    const float* __restrict__ qUw, const float* __restrict__ qUb,
    const float* __restrict__ kLw, const float* __restrict__ kLb)
{
    __shared__ float wst[PC * PR];   // transposed: wst[c*8+r]
    __shared__ float bs[PR];

    int slot = blockIdx.y;
    int d = slot >> 2, b = (slot >> 1) & 1, proj = slot & 1;
    const float *w, *bias, *x;
    if (d == 0) {
        if (proj == 0) { w = qLw; bias = qLb; x = fL; }
        else           { w = kUw; bias = kUb; x = fU; }
    } else {
        if (proj == 0) { w = qUw; bias = qUb; x = fU; }
        else           { w = kLw; bias = kLb; x = fL; }
    }
    int t = threadIdx.x;
    #pragma unroll
    for (int r = 0; r < PR; r++) wst[t * PR + r] = w[r * PC + t];
    if (t < PR) bs[t] = bias[t];
    __syncthreads();

    int n = blockIdx.x * 256 + t;
    const float* xb = x + b * (PC * PN);
    float acc[PR];
    #pragma unroll
    for (int r = 0; r < PR; r++) acc[r] = bs[r];

    #pragma unroll 4
    for (int c = 0; c < PC; c++) {
        float xv = xb[c * PN + n];
        float4 w0 = *(const float4*)&wst[c * PR];
        float4 w1 = *(const float4*)&wst[c * PR + 4];
        acc[0] = fmaf(w0.x, xv, acc[0]);
        acc[1] = fmaf(w0.y, xv, acc[1]);
        acc[2] = fmaf(w0.z, xv, acc[2]);
        acc[3] = fmaf(w0.w, xv, acc[3]);
        acc[4] = fmaf(w1.x, xv, acc[4]);
        acc[5] = fmaf(w1.y, xv, acc[5]);
        acc[6] = fmaf(w1.z, xv, acc[6]);
        acc[7] = fmaf(w1.w, xv, acc[7]);
    }

    int p = d * 2 + b;
    if (proj == 0) {
        #pragma unroll
        for (int r = 0; r < PR; r++) g_q[p][r * PN + n] = acc[r];
    } else {
        float4 o0 = make_float4(acc[0], acc[1], acc[2], acc[3]);
        float4 o1 = make_float4(acc[4], acc[5], acc[6], acc[7]);
        *(float4*)&g_k[p][n * PR]     = o0;
        *(float4*)&g_k[p][n * PR + 4] = o1;
    }
}

// ---------------------------------------------------------------------------
// K2: per-row softmax stats. One warp per row n: mx[n]=max_m s, invl[n]=1/sum exp(s-mx)
// grid (PN/8, 4 probs), block 256 (8 warps)
// ---------------------------------------------------------------------------
__device__ __forceinline__ float dot8(const float* qr, const float* kp) {
    float4 k0 = *(const float4*)kp;
    float4 k1 = *(const float4*)(kp + 4);
    float s = qr[0] * k0.x;
    s = fmaf(qr[1], k0.y, s);
    s = fmaf(qr[2], k0.z, s);
    s = fmaf(qr[3], k0.w, s);
    s = fmaf(qr[4], k1.x, s);
    s = fmaf(qr[5], k1.y, s);
    s = fmaf(qr[6], k1.z, s);
    s = fmaf(qr[7], k1.w, s);
    return s;
}

__global__ __launch_bounds__(256) void k2_stats()
{
    int p = blockIdx.y;
    int warp = threadIdx.x >> 5, lane = threadIdx.x & 31;
    int n = blockIdx.x * 8 + warp;
    const float* qg = g_q[p];
    const float* kg = g_k[p];

    float qr[PR];
    #pragma unroll
    for (int r = 0; r < PR; r++) qr[r] = qg[r * PN + n];

    float mloc = -1e30f;
    for (int m = lane; m < PN; m += 32) {
        float s = dot8(qr, &kg[m * PR]);
        mloc = fmaxf(mloc, s);
    }
    #pragma unroll
    for (int o = 16; o; o >>= 1)
        mloc = fmaxf(mloc, __shfl_xor_sync(0xFFFFFFFFu, mloc, o));

    float l = 0.0f;
    for (int m = lane; m < PN; m += 32) {
        float s = dot8(qr, &kg[m * PR]);
        l += __expf(s - mloc);
    }
    #pragma unroll
    for (int o = 16; o; o >>= 1)
        l += __shfl_xor_sync(0xFFFFFFFFu, l, o);

    if (lane == 0) {
        g_mx[p][n] = mloc;
        g_invl[p][n] = 1.0f / l;
    }
}

// ---------------------------------------------------------------------------
// K3: grouped 1x1 conv + invl scaling, output transposed:
//   vhat[n][c] = (sum_i w[g][co][i] * x[(g*64+i)][n] + vb[c]) * invl[n]
// grid (PN/64, 4 groups, 4 probs), block 256 (4x4 microtile per thread)
// ---------------------------------------------------------------------------
__global__ __launch_bounds__(256) void k3_v(
    const float* __restrict__ fL, const float* __restrict__ fU,
    const float* __restrict__ vUw, const float* __restrict__ vUb,
    const float* __restrict__ vLw, const float* __restrict__ vLb)
{
    __shared__ float wsT[CG * 65];   // wsT[i*65 + co]

    int p = blockIdx.z;
    int d = p >> 1, b = p & 1;
    int g = blockIdx.y;
    int n0 = blockIdx.x * 64;

    const float* w  = (d == 0) ? vUw : vLw;
    const float* vb = (d == 0) ? vUb : vLb;
    const float* x  = ((d == 0) ? fU : fL) + b * (PC * PN);

    int t = threadIdx.x;
    #pragma unroll
    for (int u = 0; u < 16; u++) {
        int lin = t + u * 256;                 // 0..4095
        int co = lin >> 6, i = lin & 63;
        wsT[i * 65 + co] = w[g * (CG * CG) + co * CG + i];
    }
    __syncthreads();

    int tx = t & 15, ty = t >> 4;
    float acc[4][4];
    #pragma unroll
    for (int j = 0; j < 4; j++)
        #pragma unroll
        for (int ii = 0; ii < 4; ii++) acc[j][ii] = 0.0f;

    const float* xg = x + g * CG * PN + n0 + ty * 4;
    #pragma unroll 8
    for (int i = 0; i < CG; i++) {
        float4 xv = *(const float4*)&xg[i * PN];
        int wb = i * 65 + tx * 4;
        float w0 = wsT[wb], w1 = wsT[wb + 1], w2 = wsT[wb + 2], w3 = wsT[wb + 3];
        acc[0][0] = fmaf(xv.x, w0, acc[0][0]);
        acc[0][1] = fmaf(xv.x, w1, acc[0][1]);
        acc[0][2] = fmaf(xv.x, w2, acc[0][2]);
        acc[0][3] = fmaf(xv.x, w3, acc[0][3]);
        acc[1][0] = fmaf(xv.y, w0, acc[1][0]);
        acc[1][1] = fmaf(xv.y, w1, acc[1][1]);
        acc[1][2] = fmaf(xv.y, w2, acc[1][2]);
        acc[1][3] = fmaf(xv.y, w3, acc[1][3]);
        acc[2][0] = fmaf(xv.z, w0, acc[2][0]);
        acc[2][1] = fmaf(xv.z, w1, acc[2][1]);
        acc[2][2] = fmaf(xv.z, w2, acc[2][2]);
        acc[2][3] = fmaf(xv.z, w3, acc[2][3]);
        acc[3][0] = fmaf(xv.w, w0, acc[3][0]);
        acc[3][1] = fmaf(xv.w, w1, acc[3][1]);
        acc[3][2] = fmaf(xv.w, w2, acc[3][2]);
        acc[3][3] = fmaf(xv.w, w3, acc[3][3]);
    }

    float bias[4];
    #pragma unroll
    for (int ii = 0; ii < 4; ii++) bias[ii] = vb[g * CG + tx * 4 + ii];

    float* vout = g_vhat[p];
    #pragma unroll
    for (int j = 0; j < 4; j++) {
        int n = n0 + ty * 4 + j;
        float il = g_invl[p][n];
        float4 o;
        o.x = (acc[j][0] + bias[0]) * il;
        o.y = (acc[j][1] + bias[1]) * il;
        o.z = (acc[j][2] + bias[2]) * il;
        o.w = (acc[j][3] + bias[3]) * il;
        *(float4*)&vout[n * PC + g * CG + tx * 4] = o;
    }
}

// ---------------------------------------------------------------------------
// K4: fused attend GEMM.  out[c,m] = f[c,m] + beta * sum_n vhat[n,c]*exp(s[n,m]-mx[n])
// 128x128 block tile, TN=32 n-chunk, 256 threads, 8x8 microtile.
// grid (PN/128 m-tiles, PC/128 c-tiles, 4 probs)
// ---------------------------------------------------------------------------
#define TN 32

__global__ __launch_bounds__(256, 2) void k4_attend(
    const float* __restrict__ fL, const float* __restrict__ fU,
    const float* __restrict__ beta_p, float* __restrict__ out)
{
    __shared__ float As[TN][128];    // vhat tile: As[ni][ci]
    __shared__ float Bs[TN][128];    // p tile:   Bs[ni][mi]
    __shared__ float qs[PR][TN];
    __shared__ float ks[PR][128];
    __shared__ float mxs[TN];

    const int t = threadIdx.x;
    const int p = blockIdx.z;
    const int d = p >> 1, b = p & 1;
    const int m0 = blockIdx.x * 128;
    const int c0 = blockIdx.y * 128;

    const float* qg  = g_q[p];
    const float* kg  = g_k[p];
    const float* vg  = g_vhat[p];
    const float* mxg = g_mx[p];

    // load K slice for this m-tile once
    #pragma unroll
    for (int u = 0; u < 4; u++) {
        int lin = t + u * 256;            // 0..1023
        int mi = lin >> 3, r = lin & 7;
        ks[r][mi] = kg[(m0 + mi) * PR + r];
    }
    __syncthreads();

    const int mi_fix = t & 127;
    float kreg[PR];
    #pragma unroll
    for (int r = 0; r < PR; r++) kreg[r] = ks[r][mi_fix];

    const int tx = t & 15, ty = t >> 4;
    float acc[8][8];
    #pragma unroll
    for (int i = 0; i < 8; i++)
        #pragma unroll
        for (int j = 0; j < 8; j++) acc[i][j] = 0.0f;

    for (int n0 = 0; n0 < PN; n0 += TN) {
        __syncthreads();   // protect smem from previous iteration's readers
        // load As (vhat tile) 32x128
        #pragma unroll
        for (int u = 0; u < 4; u++) {
            int lin = t + u * 256;         // 0..1023 float4s
            int row = lin >> 5, colv = lin & 31;
            *(float4*)&As[row][colv * 4] =
                *(const float4*)&vg[(n0 + row) * PC + c0 + colv * 4];
        }
        // load q slice 8x32 and mx
        {
            int r = t >> 5, ni = t & 31;
            qs[r][ni] = qg[r * PN + n0 + ni];
        }
        if (t < TN) mxs[t] = mxg[n0 + t];
        __syncthreads();

        // compute p tile: Bs[ni][mi] = exp(q.k - mx)
        #pragma unroll
        for (int v = 0; v < 16; v++) {
            int ni = ((t >> 7) + 2 * v) & 31;
            float s = -mxs[ni];
            #pragma unroll
            for (int r = 0; r < PR; r++) s = fmaf(qs[r][ni], kreg[r], s);
            Bs[ni][mi_fix] = __expf(s);
        }
        __syncthreads();

        // GEMM accumulate
        #pragma unroll 8
        for (int kk = 0; kk < TN; kk++) {
            float a[8], bb[8];
            *(float4*)&a[0]  = *(float4*)&As[kk][ty * 4];
            *(float4*)&a[4]  = *(float4*)&As[kk][64 + ty * 4];
            *(float4*)&bb[0] = *(float4*)&Bs[kk][tx * 4];
            *(float4*)&bb[4] = *(float4*)&Bs[kk][64 + tx * 4];
            #pragma unroll
            for (int i = 0; i < 8; i++)
                #pragma unroll
                for (int j = 0; j < 8; j++)
                    acc[i][j] = fmaf(a[i], bb[j], acc[i][j]);
        }
    }

    // epilogue: out = f + beta * acc
    const float beta = __ldg(beta_p);
    const float* fb = ((d == 0) ? fL : fU) + b * (PC * PN);
    float* ob = out + d * (PB * PC * PN) + b * (PC * PN);

    #pragma unroll
    for (int ih = 0; ih < 2; ih++) {
        #pragma unroll
        for (int i = 0; i < 4; i++) {
            int c = c0 + ih * 64 + ty * 4 + i;
            #pragma unroll
            for (int jh = 0; jh < 2; jh++) {
                int m = m0 + jh * 64 + tx * 4;
                float4 f4 = *(const float4*)&fb[c * PN + m];
                float4 o;
                o.x = fmaf(beta, acc[ih * 4 + i][jh * 4 + 0], f4.x);
                o.y = fmaf(beta, acc[ih * 4 + i][jh * 4 + 1], f4.y);
                o.z = fmaf(beta, acc[ih * 4 + i][jh * 4 + 2], f4.z);
                o.w = fmaf(beta, acc[ih * 4 + i][jh * 4 + 3], f4.w);
                *(float4*)&ob[c * PN + m] = o;
            }
        }
    }
}

// ---------------------------------------------------------------------------
extern "C" void kernel_launch(void* const* d_in, const int* in_sizes, int n_in,
                              void* d_out, int out_size)
{
    const float* fL  = (const float*)d_in[0];
    const float* fU  = (const float*)d_in[1];
    const float* qLw = (const float*)d_in[2];
    const float* qLb = (const float*)d_in[3];
    const float* kUw = (const float*)d_in[4];
    const float* kUb = (const float*)d_in[5];
    const float* vUw = (const float*)d_in[6];
    const float* vUb = (const float*)d_in[7];
    const float* qUw = (const float*)d_in[8];
    const float* qUb = (const float*)d_in[9];
    const float* kLw = (const float*)d_in[10];
    const float* kLb = (const float*)d_in[11];
    const float* vLw = (const float*)d_in[12];
    const float* vLb = (const float*)d_in[13];
    const float* beta = (const float*)d_in[14];
    float* out = (float*)d_out;

    k1_qk<<<dim3(PN / 256, 8), 256>>>(fL, fU, qLw, qLb, kUw, kUb, qUw, qUb, kLw, kLb);
    k2_stats<<<dim3(PN / 8, 4), 256>>>();
    k3_v<<<dim3(PN / 64, PG, 4), 256>>>(fL, fU, vUw, vUb, vLw, vLb);
    k4_attend<<<dim3(PN / 128, PC / 128, 4), 256>>>(fL, fU, beta, out);
}